// round 13
// baseline (speedup 1.0000x reference)
#include <cuda_runtime.h>
#include <cstdint>

// Dice loss: pred (8,62,512,512) f32 logits, target (8,512,512) i32 -> scalar f32.
// Single HBM pass (520MB), single launch.
// R12 vs R11 (98.3us wall, DRAM 75.5%, 12 warps/SM):
//  - restore 16 warps/SM (2x256-thread CTAs, 304 blocks) by cutting regs to ~120:
//      pixel0 exp values: 31 bf16x2 regs (class-pair packed)
//      pixel1 exp values: staged in shared memory (conflict-free lane-stride layout)
//  - keep: float2 loads, et via L2 reload, packed K=512 shared atomic, fused finish

#define NC      62
#define NCH     31             // class pairs
#define HWV     (512 * 512)
#define NPIX    (8 * 512 * 512)
#define NQ      (NPIX / 2)
#define IGNORE  255
#define NBLK    304            // 2 CTAs/SM x 152 SMs
#define NW      8              // warps per CTA
#define KP      512.0f
#define KPINV   (1.0f / 512.0f)

__device__ float g_pred_part[NC * NBLK];   // [c][b] per-CTA sum of softmax probs
__device__ float g_ic_part[NC * NBLK];     // [c][b] packed: KP*count + inter
__device__ unsigned g_ticket;              // zero-init; last CTA resets to 0

__global__ __launch_bounds__(256, 2)
void dice_main(const float* __restrict__ pred, const int* __restrict__ target,
               float* __restrict__ out) {
    __shared__ uint32_t smem_e[NCH][256];  // pixel1 exp values, bf16x2 per class pair
    __shared__ float s_ic[NC];             // packed inter+count, per class
    __shared__ float s1[NW][NC];           // per-warp staging for acc1 reduction
    __shared__ float sh_ds[NC];
    __shared__ float sh_nv[NC];
    __shared__ bool  s_last;

    const int tid = threadIdx.x;
    for (int i = tid; i < NC; i += 256) s_ic[i] = 0.f;
    __syncthreads();

    float acc1[NC];                // per-class sum of softmax probs (valid pixels)
#pragma unroll
    for (int c = 0; c < NC; ++c) acc1[c] = 0.f;

    const float L2E = 1.4426950408889634f;
    const int stride = gridDim.x * blockDim.x;

    for (int q = blockIdx.x * blockDim.x + tid; q < NQ; q += stride) {
        const int p  = q << 1;               // first pixel of the pair
        const int n  = p >> 18;
        const int hw = p & (HWV - 1);        // even -> float2 aligned
        const float* base = pred + (size_t)n * (NC * HWV) + hw;

        const int2 tt = *(const int2*)(target + p);
        const bool v0 = (tt.x != IGNORE);
        const bool v1 = (tt.y != IGNORE);
        const int  t0 = v0 ? tt.x : 0;
        const int  t1 = v1 ? tt.y : 0;

        // logits at target class (lines fetched this iteration -> L2 hits)
        const float xt0 = __ldg(base + (size_t)t0 * HWV);
        const float xt1 = __ldg(base + (size_t)t1 * HWV + 1);

        uint32_t epk[NCH];         // pixel0: bf16x2 {hi=class c+1, lo=class c}
        float d0 = 0.f, d1 = 0.f;

#pragma unroll
        for (int j = 0; j < NCH; ++j) {
            const int c = j << 1;
            const float2 xa = __ldcs((const float2*)(base + (size_t)c * HWV));       // class c,  pix 0/1
            const float2 xb = __ldcs((const float2*)(base + (size_t)(c + 1) * HWV)); // class c+1, pix 0/1
            float e0a, e0b, e1a, e1b;
            asm("ex2.approx.ftz.f32 %0, %1;" : "=f"(e0a) : "f"(xa.x * L2E));
            asm("ex2.approx.ftz.f32 %0, %1;" : "=f"(e1a) : "f"(xa.y * L2E));
            asm("ex2.approx.ftz.f32 %0, %1;" : "=f"(e0b) : "f"(xb.x * L2E));
            asm("ex2.approx.ftz.f32 %0, %1;" : "=f"(e1b) : "f"(xb.y * L2E));
            d0 += e0a + e0b;
            d1 += e1a + e1b;
            uint32_t pk0, pk1;
            asm("cvt.rn.bf16x2.f32 %0, %1, %2;" : "=r"(pk0) : "f"(e0b), "f"(e0a));
            asm("cvt.rn.bf16x2.f32 %0, %1, %2;" : "=r"(pk1) : "f"(e1b), "f"(e1a));
            epk[j] = pk0;
            smem_e[j][tid] = pk1;   // stage pixel1 in shared (conflict-free)
        }

        float inv0, inv1;
        asm("rcp.approx.ftz.f32 %0, %1;" : "=f"(inv0) : "f"(d0));
        asm("rcp.approx.ftz.f32 %0, %1;" : "=f"(inv1) : "f"(d1));
        const float i0 = v0 ? inv0 : 0.f;
        const float i1 = v1 ? inv1 : 0.f;

        // prob at target + packed count: one shared atomic per valid pixel
        float et0, et1;
        asm("ex2.approx.ftz.f32 %0, %1;" : "=f"(et0) : "f"(xt0 * L2E));
        asm("ex2.approx.ftz.f32 %0, %1;" : "=f"(et1) : "f"(xt1 * L2E));
        if (v0) atomicAdd(&s_ic[t0], fmaf(et0, inv0, KP));
        if (v1) atomicAdd(&s_ic[t1], fmaf(et1, inv1, KP));

#pragma unroll
        for (int j = 0; j < NCH; ++j) {
            const int c = j << 1;
            const uint32_t pk0 = epk[j];
            const uint32_t pk1 = smem_e[j][tid];
            const float e0a = __uint_as_float(pk0 << 16);
            const float e0b = __uint_as_float(pk0 & 0xffff0000u);
            const float e1a = __uint_as_float(pk1 << 16);
            const float e1b = __uint_as_float(pk1 & 0xffff0000u);
            acc1[c]     = fmaf(e0a, i0, fmaf(e1a, i1, acc1[c]));
            acc1[c + 1] = fmaf(e0b, i0, fmaf(e1b, i1, acc1[c + 1]));
        }
    }

    // Reduce acc1: warp butterfly per class -> shared -> per-CTA global slot.
    const int lane = tid & 31;
    const int w    = tid >> 5;
#pragma unroll
    for (int c = 0; c < NC; ++c) {
        float v = acc1[c];
#pragma unroll
        for (int s = 16; s; s >>= 1) v += __shfl_xor_sync(0xffffffffu, v, s);
        if (lane == 0) s1[w][c] = v;
    }
    __syncthreads();

    for (int c = tid; c < NC; c += 256) {
        float a = 0.f;
#pragma unroll
        for (int ww = 0; ww < NW; ++ww) a += s1[ww][c];
        g_pred_part[c * NBLK + blockIdx.x] = a;
        g_ic_part[c * NBLK + blockIdx.x]   = s_ic[c];
    }

    // ---- threadfence reduction: last CTA does the final reduce ----
    __threadfence();
    if (tid == 0) {
        const unsigned tk = atomicAdd(&g_ticket, 1u);
        s_last = (tk == NBLK - 1);
    }
    __syncthreads();
    if (!s_last) return;

    __threadfence();  // acquire: all CTAs' partials visible

    // 8 warps; warp w handles classes c = w, w+8, ... (L2-resident reads)
    for (int c = w; c < NC; c += NW) {
        float sp = 0.f, si = 0.f, sc = 0.f;
#pragma unroll
        for (int b = lane; b < NBLK; b += 32) {
            sp += g_pred_part[c * NBLK + b];
            const float v  = g_ic_part[c * NBLK + b];
            const float cf = floorf(v * KPINV);
            si = fmaf(-KP, cf, v) + si;   // inter part
            sc += cf;                      // count part
        }
#pragma unroll
        for (int s = 16; s; s >>= 1) {
            sp += __shfl_xor_sync(0xffffffffu, sp, s);
            si += __shfl_xor_sync(0xffffffffu, si, s);
            sc += __shfl_xor_sync(0xffffffffu, sc, s);
        }
        if (lane == 0) {
            const float u    = sp + sc;
            const float dice = (2.f * si + 1e-6f) / (u + 1e-6f);
            sh_ds[c] = (u > 0.f) ? dice : 0.f;
            sh_nv[c] = (u > 0.f) ? 1.f : 0.f;
        }
    }
    __syncthreads();
    if (tid == 0) {
        float ds = 0.f, nv = 0.f;
#pragma unroll
        for (int k = 0; k < NC; ++k) { ds += sh_ds[k]; nv += sh_nv[k]; }
        const float md = (nv > 0.f) ? (ds / fmaxf(nv, 1.f)) : 1.f;
        out[0] = 1.f - md;
        g_ticket = 0;   // reset for next graph replay
    }
}

extern "C" void kernel_launch(void* const* d_in, const int* in_sizes, int n_in,
                              void* d_out, int out_size) {
    const float* pred   = (const float*)d_in[0];
    const int*   target = (const int*)d_in[1];
    float*       out    = (float*)d_out;

    dice_main<<<NBLK, 256>>>(pred, target, out);
}

// round 14
// speedup vs baseline: 1.1116x; 1.1116x over previous
#include <cuda_runtime.h>
#include <cuda_fp16.h>
#include <cstdint>

// Dice loss: pred (8,62,512,512) f32 logits, target (8,512,512) i32 -> scalar f32.
// Single HBM pass (520MB), single launch.
// R13 vs R12 (119us: smem staging doubled L1 wavefronts -> regression):
//  - NO smem staging. 2 pixels/thread, float2 loads (R11 diet)
//  - exp values: fp16x2 class-pair packed, epk0[31]+epk1[31] regs
//  - accumulators: half2 acc_h[31] via HFMA2 (replaces fp32 acc1[62] + unpack LOPs)
//    -> ~115 loop regs -> 2 CTAs/SM, 16 warps/SM (R9 occupancy + R11 instr count)
//  - fp32 flush once after the main loop; reduction path unchanged

#define NC      62
#define NCH     31             // class pairs
#define HWV     (512 * 512)
#define NPIX    (8 * 512 * 512)
#define NQ      (NPIX / 2)
#define IGNORE  255
#define NBLK    304            // 2 CTAs/SM x 152 SMs
#define NW      8              // warps per CTA
#define KP      512.0f
#define KPINV   (1.0f / 512.0f)

__device__ float g_pred_part[NC * NBLK];   // [c][b] per-CTA sum of softmax probs
__device__ float g_ic_part[NC * NBLK];     // [c][b] packed: KP*count + inter
__device__ unsigned g_ticket;              // zero-init; last CTA resets to 0

__global__ __launch_bounds__(256, 2)
void dice_main(const float* __restrict__ pred, const int* __restrict__ target,
               float* __restrict__ out) {
    __shared__ float s_ic[NC];             // packed inter+count, per class
    __shared__ float s1[NW][NC];           // per-warp staging for final reduction
    __shared__ float sh_ds[NC];
    __shared__ float sh_nv[NC];
    __shared__ bool  s_last;

    const int tid = threadIdx.x;
    for (int i = tid; i < NC; i += 256) s_ic[i] = 0.f;
    __syncthreads();

    __half2 acc_h[NCH];        // packed {class 2j, class 2j+1} prob sums (fp16)
#pragma unroll
    for (int j = 0; j < NCH; ++j) acc_h[j] = __half2half2(__float2half_rn(0.f));

    const float L2E = 1.4426950408889634f;
    const int stride = gridDim.x * blockDim.x;

    for (int q = blockIdx.x * blockDim.x + tid; q < NQ; q += stride) {
        const int p  = q << 1;               // first pixel of the pair
        const int n  = p >> 18;
        const int hw = p & (HWV - 1);        // even -> float2 aligned
        const float* base = pred + (size_t)n * (NC * HWV) + hw;

        const int2 tt = *(const int2*)(target + p);
        const bool v0 = (tt.x != IGNORE);
        const bool v1 = (tt.y != IGNORE);
        const int  t0 = v0 ? tt.x : 0;
        const int  t1 = v1 ? tt.y : 0;

        // logits at target class (lines fetched this iteration -> L2 hits)
        const float xt0 = __ldg(base + (size_t)t0 * HWV);
        const float xt1 = __ldg(base + (size_t)t1 * HWV + 1);

        __half2 epk0[NCH];     // pixel0: {e[2j], e[2j+1]}
        __half2 epk1[NCH];     // pixel1: {e[2j], e[2j+1]}
        float d0a = 0.f, d0b = 0.f, d1a = 0.f, d1b = 0.f;

#pragma unroll
        for (int j = 0; j < NCH; ++j) {
            const int c = j << 1;
            const float2 xa = __ldcs((const float2*)(base + (size_t)c * HWV));       // class c,  pix 0/1
            const float2 xb = __ldcs((const float2*)(base + (size_t)(c + 1) * HWV)); // class c+1, pix 0/1
            float e0a, e0b, e1a, e1b;
            asm("ex2.approx.ftz.f32 %0, %1;" : "=f"(e0a) : "f"(xa.x * L2E));
            asm("ex2.approx.ftz.f32 %0, %1;" : "=f"(e1a) : "f"(xa.y * L2E));
            asm("ex2.approx.ftz.f32 %0, %1;" : "=f"(e0b) : "f"(xb.x * L2E));
            asm("ex2.approx.ftz.f32 %0, %1;" : "=f"(e1b) : "f"(xb.y * L2E));
            d0a += e0a; d0b += e0b;
            d1a += e1a; d1b += e1b;
            epk0[j] = __floats2half2_rn(e0a, e0b);
            epk1[j] = __floats2half2_rn(e1a, e1b);
        }

        float inv0, inv1;
        asm("rcp.approx.ftz.f32 %0, %1;" : "=f"(inv0) : "f"(d0a + d0b));
        asm("rcp.approx.ftz.f32 %0, %1;" : "=f"(inv1) : "f"(d1a + d1b));
        const float i0 = v0 ? inv0 : 0.f;
        const float i1 = v1 ? inv1 : 0.f;

        // prob at target + packed count: one shared atomic per valid pixel
        float et0, et1;
        asm("ex2.approx.ftz.f32 %0, %1;" : "=f"(et0) : "f"(xt0 * L2E));
        asm("ex2.approx.ftz.f32 %0, %1;" : "=f"(et1) : "f"(xt1 * L2E));
        if (v0) atomicAdd(&s_ic[t0], fmaf(et0, inv0, KP));
        if (v1) atomicAdd(&s_ic[t1], fmaf(et1, inv1, KP));

        const __half2 hi0 = __half2half2(__float2half_rn(i0));
        const __half2 hi1 = __half2half2(__float2half_rn(i1));
#pragma unroll
        for (int j = 0; j < NCH; ++j)
            acc_h[j] = __hfma2(epk0[j], hi0, __hfma2(epk1[j], hi1, acc_h[j]));
    }

    // Flush fp16 accumulators to fp32 (only live after the main loop).
    float acc1[NC];
#pragma unroll
    for (int j = 0; j < NCH; ++j) {
        const float2 f = __half22float2(acc_h[j]);
        acc1[2 * j]     = f.x;
        acc1[2 * j + 1] = f.y;
    }

    // Reduce acc1: warp butterfly per class -> shared -> per-CTA global slot.
    const int lane = tid & 31;
    const int w    = tid >> 5;
#pragma unroll
    for (int c = 0; c < NC; ++c) {
        float v = acc1[c];
#pragma unroll
        for (int s = 16; s; s >>= 1) v += __shfl_xor_sync(0xffffffffu, v, s);
        if (lane == 0) s1[w][c] = v;
    }
    __syncthreads();

    for (int c = tid; c < NC; c += 256) {
        float a = 0.f;
#pragma unroll
        for (int ww = 0; ww < NW; ++ww) a += s1[ww][c];
        g_pred_part[c * NBLK + blockIdx.x] = a;
        g_ic_part[c * NBLK + blockIdx.x]   = s_ic[c];
    }

    // ---- threadfence reduction: last CTA does the final reduce ----
    __threadfence();
    if (tid == 0) {
        const unsigned tk = atomicAdd(&g_ticket, 1u);
        s_last = (tk == NBLK - 1);
    }
    __syncthreads();
    if (!s_last) return;

    __threadfence();  // acquire: all CTAs' partials visible

    // 8 warps; warp w handles classes c = w, w+8, ... (L2-resident reads)
    for (int c = w; c < NC; c += NW) {
        float sp = 0.f, si = 0.f, sc = 0.f;
#pragma unroll
        for (int b = lane; b < NBLK; b += 32) {
            sp += g_pred_part[c * NBLK + b];
            const float v  = g_ic_part[c * NBLK + b];
            const float cf = floorf(v * KPINV);
            si = fmaf(-KP, cf, v) + si;   // inter part
            sc += cf;                      // count part
        }
#pragma unroll
        for (int s = 16; s; s >>= 1) {
            sp += __shfl_xor_sync(0xffffffffu, sp, s);
            si += __shfl_xor_sync(0xffffffffu, si, s);
            sc += __shfl_xor_sync(0xffffffffu, sc, s);
        }
        if (lane == 0) {
            const float u    = sp + sc;
            const float dice = (2.f * si + 1e-6f) / (u + 1e-6f);
            sh_ds[c] = (u > 0.f) ? dice : 0.f;
            sh_nv[c] = (u > 0.f) ? 1.f : 0.f;
        }
    }
    __syncthreads();
    if (tid == 0) {
        float ds = 0.f, nv = 0.f;
#pragma unroll
        for (int k = 0; k < NC; ++k) { ds += sh_ds[k]; nv += sh_nv[k]; }
        const float md = (nv > 0.f) ? (ds / fmaxf(nv, 1.f)) : 1.f;
        out[0] = 1.f - md;
        g_ticket = 0;   // reset for next graph replay
    }
}

extern "C" void kernel_launch(void* const* d_in, const int* in_sizes, int n_in,
                              void* d_out, int out_size) {
    const float* pred   = (const float*)d_in[0];
    const int*   target = (const int*)d_in[1];
    float*       out    = (float*)d_out;

    dice_main<<<NBLK, 256>>>(pred, target, out);
}